// round 9
// baseline (speedup 1.0000x reference)
#include <cuda_runtime.h>

#define STRIDE   4
#define CIN      96
#define COUT     192
#define TM       64          // windows per block
#define THREADS  256
#define MAXB     16

// smem: W (CIN*COUT f32) + pooled feat tile (TM*CIN f32) + window meta
#define SMEM_BYTES ((CIN*COUT + TM*CIN) * sizeof(float) + 2 * TM * sizeof(int))

__global__ __launch_bounds__(THREADS, 2)
void down_block_kernel(const float* __restrict__ feat,
                       const float* __restrict__ coord,
                       const float* __restrict__ scores,
                       const float* __restrict__ W,
                       const float* __restrict__ bias,
                       const int*   __restrict__ lengths,
                       int B,
                       float* __restrict__ out)
{
    extern __shared__ float smem[];
    float* Ws = smem;                       // [CIN*COUT]
    float* Fs = Ws + CIN * COUT;            // [TM*CIN]
    int*   wstart = (int*)(Fs + TM * CIN);  // [TM]
    int*   wcnt   = wstart + TM;            // [TM]
    __shared__ long long sM;                // total number of windows

    const int tid = threadIdx.x;
    const long long m0 = (long long)blockIdx.x * TM;

    // ---- stage W into smem (float4) ----
    {
        const float4* Wv  = (const float4*)W;
        float4*       Wsv = (float4*)Ws;
        #pragma unroll 4
        for (int i = tid; i < CIN * COUT / 4; i += THREADS)
            Wsv[i] = Wv[i];
    }

    // ---- per-window metadata + small outputs ----
    if (tid < TM) {
        long long off = 0, woff = 0;
        const long long m = m0 + tid;
        int st = 0, cnt = 0, bidx = 0;
        #pragma unroll
        for (int b = 0; b < MAXB; b++) {
            if (b >= B) break;
            long long L  = (long long)lengths[b];
            long long nw = (L + STRIDE - 1) / STRIDE;
            if (m >= woff && m < woff + nw) {
                long long s = off + (m - woff) * STRIDE;
                long long e = off + L;
                st   = (int)s;
                long long c = e - s; if (c > STRIDE) c = STRIDE;
                cnt  = (int)c;
                bidx = b;
            }
            off  += L;
            woff += nw;
        }
        const long long Mtot = woff;
        if (tid == 0) sM = Mtot;
        wstart[tid] = st;
        wcnt[tid]   = cnt;

        if (cnt > 0) {
            float* c_out = out + Mtot * COUT;          // coord_down [M,3]
            float* b_out = c_out + Mtot * 3;           // batch_down [M]
            float* s_out = b_out + Mtot;               // scores_down [M]
            const float inv = 1.0f / (float)cnt;
            float cx = 0.f, cy = 0.f, cz = 0.f, sc = 0.f;
            for (int p = 0; p < cnt; p++) {
                const float* cp = coord + (long long)(st + p) * 3;
                cx += cp[0]; cy += cp[1]; cz += cp[2];
                sc += scores[st + p];
            }
            c_out[m * 3 + 0] = cx * inv;
            c_out[m * 3 + 1] = cy * inv;
            c_out[m * 3 + 2] = cz * inv;
            s_out[m] = sc * inv;
            b_out[m] = (float)bidx;
        }

        // lengths_down + offset_down (block 0 only)
        if (blockIdx.x == 0 && tid < B) {
            long long cum = 0, nw_me = 0;
            for (int b = 0; b <= tid; b++) {
                long long L = (long long)lengths[b];
                nw_me = (L + STRIDE - 1) / STRIDE;
                cum  += nw_me;
            }
            float* len_out = out + Mtot * (COUT + 5);  // 192 + 3 + 1 + 1
            float* off_out = len_out + B;
            len_out[tid] = (float)nw_me;
            off_out[tid] = (float)cum;
        }
    }
    __syncthreads();
    const long long M = sM;

    // ---- pooled feat tile -> smem ----
    #pragma unroll 2
    for (int idx = tid; idx < TM * CIN; idx += THREADS) {
        const int w = idx / CIN;
        const int c = idx - w * CIN;
        const int cnt = wcnt[w];
        float v = 0.f;
        if (cnt == STRIDE) {
            const float* fp = feat + (long long)wstart[w] * CIN + c;
            v = (fp[0] + fp[CIN]) + (fp[2 * CIN] + fp[3 * CIN]);
            v *= (1.0f / STRIDE);
        } else if (cnt > 0) {
            const float* fp = feat + (long long)wstart[w] * CIN + c;
            for (int p = 0; p < cnt; p++) v += fp[p * CIN];
            v *= 1.0f / (float)cnt;
        }
        Fs[idx] = v;
    }
    __syncthreads();

    // ---- register-tiled GEMM: 64x192 = (8 warps x 8 rows) x (32 lanes x 6 cols) ----
    const int tx = tid & 31;      // col group: cols {tx + 32*j}
    const int ty = tid >> 5;      // row strip: rows {ty*8 .. ty*8+7}

    float acc[8][6];
    #pragma unroll
    for (int i = 0; i < 8; i++)
        #pragma unroll
        for (int j = 0; j < 6; j++) acc[i][j] = 0.f;

    float bb[6];
    #pragma unroll
    for (int j = 0; j < 6; j++) bb[j] = bias[tx + 32 * j];

    const float* FsRow = Fs + (ty * 8) * CIN;

    #pragma unroll 4
    for (int k = 0; k < CIN; k++) {
        float bv[6];
        #pragma unroll
        for (int j = 0; j < 6; j++) bv[j] = Ws[k * COUT + tx + 32 * j];
        #pragma unroll
        for (int i = 0; i < 8; i++) {
            const float av = FsRow[i * CIN + k];   // warp-broadcast
            #pragma unroll
            for (int j = 0; j < 6; j++)
                acc[i][j] = fmaf(av, bv[j], acc[i][j]);
        }
    }

    // ---- epilogue: bias + ReLU, coalesced STG ----
    #pragma unroll
    for (int i = 0; i < 8; i++) {
        const long long m = m0 + ty * 8 + i;
        if (m < M) {
            float* row = out + m * COUT;
            #pragma unroll
            for (int j = 0; j < 6; j++)
                row[tx + 32 * j] = fmaxf(acc[i][j] + bb[j], 0.0f);
        }
    }
}

extern "C" void kernel_launch(void* const* d_in, const int* in_sizes, int n_in,
                              void* d_out, int out_size)
{
    const float* feat    = (const float*)d_in[0];
    const float* coord   = (const float*)d_in[1];
    const float* scores  = (const float*)d_in[2];
    const float* W       = (const float*)d_in[3];
    const float* bias    = (const float*)d_in[4];
    const int*   lengths = (const int*)  d_in[5];
    const int B = in_sizes[5];
    const long long N = (long long)in_sizes[2];   // scores element count == N points

    const long long M_upper = (N + STRIDE - 1) / STRIDE + B;
    const int blocks = (int)((M_upper + TM - 1) / TM);

    cudaFuncSetAttribute(down_block_kernel,
                         cudaFuncAttributeMaxDynamicSharedMemorySize,
                         (int)SMEM_BYTES);

    down_block_kernel<<<blocks, THREADS, SMEM_BYTES>>>(
        feat, coord, scores, W, bias, lengths, B, (float*)d_out);
}

// round 10
// speedup vs baseline: 1.0039x; 1.0039x over previous
#include <cuda_runtime.h>

#define STRIDE   4
#define CIN      96
#define COUT     192
#define TM       64          // windows per block
#define THREADS  256
#define MAXB     16

// smem: W (CIN*COUT f32) + pooled feat tile (TM*CIN f32) + window meta
#define SMEM_BYTES ((CIN*COUT + TM*CIN) * sizeof(float) + 2 * TM * sizeof(int))

__global__ __launch_bounds__(THREADS, 2)
void down_block_kernel(const float* __restrict__ feat,
                       const float* __restrict__ coord,
                       const float* __restrict__ scores,
                       const float* __restrict__ W,
                       const float* __restrict__ bias,
                       const int*   __restrict__ lengths,
                       int B,
                       float* __restrict__ out)
{
    extern __shared__ float smem[];
    float* Ws = smem;                       // [CIN*COUT]
    float* Fs = Ws + CIN * COUT;            // [TM*CIN]
    int*   wstart = (int*)(Fs + TM * CIN);  // [TM]
    int*   wcnt   = wstart + TM;            // [TM]
    __shared__ long long sM;                // total number of windows

    const int tid = threadIdx.x;
    const long long m0 = (long long)blockIdx.x * TM;

    // ---- stage W into smem (float4) ----
    {
        const float4* Wv  = (const float4*)W;
        float4*       Wsv = (float4*)Ws;
        #pragma unroll 4
        for (int i = tid; i < CIN * COUT / 4; i += THREADS)
            Wsv[i] = Wv[i];
    }

    // ---- per-window metadata + small outputs ----
    if (tid < TM) {
        long long off = 0, woff = 0;
        const long long m = m0 + tid;
        int st = 0, cnt = 0, bidx = 0;
        #pragma unroll
        for (int b = 0; b < MAXB; b++) {
            if (b >= B) break;
            long long L  = (long long)lengths[b];
            long long nw = (L + STRIDE - 1) / STRIDE;
            if (m >= woff && m < woff + nw) {
                long long s = off + (m - woff) * STRIDE;
                long long e = off + L;
                st   = (int)s;
                long long c = e - s; if (c > STRIDE) c = STRIDE;
                cnt  = (int)c;
                bidx = b;
            }
            off  += L;
            woff += nw;
        }
        const long long Mtot = woff;
        if (tid == 0) sM = Mtot;
        wstart[tid] = st;
        wcnt[tid]   = cnt;

        if (cnt > 0) {
            float* c_out = out + Mtot * COUT;          // coord_down [M,3]
            float* b_out = c_out + Mtot * 3;           // batch_down [M]
            float* s_out = b_out + Mtot;               // scores_down [M]
            const float inv = 1.0f / (float)cnt;
            float cx = 0.f, cy = 0.f, cz = 0.f, sc = 0.f;
            for (int p = 0; p < cnt; p++) {
                const float* cp = coord + (long long)(st + p) * 3;
                cx += cp[0]; cy += cp[1]; cz += cp[2];
                sc += scores[st + p];
            }
            c_out[m * 3 + 0] = cx * inv;
            c_out[m * 3 + 1] = cy * inv;
            c_out[m * 3 + 2] = cz * inv;
            s_out[m] = sc * inv;
            b_out[m] = (float)bidx;
        }

        // lengths_down + offset_down (block 0 only)
        if (blockIdx.x == 0 && tid < B) {
            long long cum = 0, nw_me = 0;
            for (int b = 0; b <= tid; b++) {
                long long L = (long long)lengths[b];
                nw_me = (L + STRIDE - 1) / STRIDE;
                cum  += nw_me;
            }
            float* len_out = out + Mtot * (COUT + 5);  // 192 + 3 + 1 + 1
            float* off_out = len_out + B;
            len_out[tid] = (float)nw_me;
            off_out[tid] = (float)cum;
        }
    }
    __syncthreads();
    const long long M = sM;

    // ---- pooled feat tile -> smem ----
    #pragma unroll 2
    for (int idx = tid; idx < TM * CIN; idx += THREADS) {
        const int w = idx / CIN;
        const int c = idx - w * CIN;
        const int cnt = wcnt[w];
        float v = 0.f;
        if (cnt == STRIDE) {
            const float* fp = feat + (long long)wstart[w] * CIN + c;
            v = (fp[0] + fp[CIN]) + (fp[2 * CIN] + fp[3 * CIN]);
            v *= (1.0f / STRIDE);
        } else if (cnt > 0) {
            const float* fp = feat + (long long)wstart[w] * CIN + c;
            for (int p = 0; p < cnt; p++) v += fp[p * CIN];
            v *= 1.0f / (float)cnt;
        }
        Fs[idx] = v;
    }
    __syncthreads();

    // ---- register-tiled GEMM: 64x192 = (8 warps x 8 rows) x (32 lanes x 6 cols) ----
    const int tx = tid & 31;      // col group: cols {tx + 32*j}
    const int ty = tid >> 5;      // row strip: rows {ty*8 .. ty*8+7}

    float acc[8][6];
    #pragma unroll
    for (int i = 0; i < 8; i++)
        #pragma unroll
        for (int j = 0; j < 6; j++) acc[i][j] = 0.f;

    float bb[6];
    #pragma unroll
    for (int j = 0; j < 6; j++) bb[j] = bias[tx + 32 * j];

    const float* FsRow = Fs + (ty * 8) * CIN;

    #pragma unroll 4
    for (int k = 0; k < CIN; k++) {
        float bv[6];
        #pragma unroll
        for (int j = 0; j < 6; j++) bv[j] = Ws[k * COUT + tx + 32 * j];
        #pragma unroll
        for (int i = 0; i < 8; i++) {
            const float av = FsRow[i * CIN + k];   // warp-broadcast
            #pragma unroll
            for (int j = 0; j < 6; j++)
                acc[i][j] = fmaf(av, bv[j], acc[i][j]);
        }
    }

    // ---- epilogue: bias + ReLU, coalesced STG ----
    #pragma unroll
    for (int i = 0; i < 8; i++) {
        const long long m = m0 + ty * 8 + i;
        if (m < M) {
            float* row = out + m * COUT;
            #pragma unroll
            for (int j = 0; j < 6; j++)
                row[tx + 32 * j] = fmaxf(acc[i][j] + bb[j], 0.0f);
        }
    }
}

extern "C" void kernel_launch(void* const* d_in, const int* in_sizes, int n_in,
                              void* d_out, int out_size)
{
    const float* feat    = (const float*)d_in[0];
    const float* coord   = (const float*)d_in[1];
    const float* scores  = (const float*)d_in[2];
    const float* W       = (const float*)d_in[3];
    const float* bias    = (const float*)d_in[4];
    const int*   lengths = (const int*)  d_in[5];
    const int B = in_sizes[5];
    const long long N = (long long)in_sizes[2];   // scores element count == N points

    const long long M_upper = (N + STRIDE - 1) / STRIDE + B;
    const int blocks = (int)((M_upper + TM - 1) / TM);

    cudaFuncSetAttribute(down_block_kernel,
                         cudaFuncAttributeMaxDynamicSharedMemorySize,
                         (int)SMEM_BYTES);

    down_block_kernel<<<blocks, THREADS, SMEM_BYTES>>>(
        feat, coord, scores, W, bias, lengths, B, (float*)d_out);
}